// round 15
// baseline (speedup 1.0000x reference)
#include <cuda_runtime.h>
#include <cuda_fp16.h>
#include <cstdint>

// ===========================================================================
// Arch-feature detection: tcgen05 exists only on 'a'/'f' feature targets.
// ===========================================================================
#define HAS_TCGEN05 0
#if defined(__CUDA_ARCH__) && (__CUDA_ARCH__ >= 1000)
#  if defined(__CUDA_ARCH_FAMILY_SPECIFIC__) || defined(__CUDA_ARCH_SPECIFIC__)
#    undef HAS_TCGEN05
#    define HAS_TCGEN05 1
#  elif defined(__CUDA_ARCH_HAS_FEATURE__)
#    if __CUDA_ARCH_HAS_FEATURE__(SM103_ALL) || __CUDA_ARCH_HAS_FEATURE__(SM100_ALL)
#      undef HAS_TCGEN05
#      define HAS_TCGEN05 1
#    endif
#  endif
#endif

// Problem constants
#define M_DIM 8192
#define N_DIM 4096
#define K_DIM 4096
#define NOUT  128
#define KE    4224            // K + NOUT (outlier GEMM fused as extra K)

// cg2 persistent tiling: 74 pairs, 256x256 pair tiles; 32x16 = 512 tiles
#define TM 128
#define TN 256
#define CH_K 64
#define NCHUNK (KE / CH_K)    // 66
#define NGROUP (NCHUNK / 2)   // 33 (2-chunk prep groups)
#define NSTAGE 6
#define NCTA 148
#define NPAIR 74
#define NTILE2 512
#define A_STG_BYTES (TM * 128)            // 16384
#define B_STG_BYTES ((TN / 2) * 128)      // 16384
#define STG_BYTES   (A_STG_BYTES + B_STG_BYTES)   // 32768
#define CTRL_OFF    (NSTAGE * STG_BYTES)          // 196608
#define SMEM_TOTAL  (CTRL_OFF + 256)

// idesc kind::f16 cg2: dtype=F32(1<<4), N=256 -> 32<<17, M=256 -> 16<<24
#define IDESC ((1u << 4) | ((TN / 8) << 17) | (16u << 24))
#define DESC_BASE ((uint64_t(2) << 61) | (uint64_t(1) << 46) | (uint64_t(64) << 32) | (uint64_t(1) << 16))

// Fallback prep partition
#define A_UNITS (NCHUNK * M_DIM * 8)
#define B_UNITS (NCHUNK * N_DIM * 8)
#define PREP_THREADS ((A_UNITS + B_UNITS) / 256)

// Scratch fp16 operands in CHUNK-MAJOR, PRE-SWIZZLED (SW128) layout:
//   byte addr of 16B unit (c, row, u) = ((c*ROWS + row)*128) + ((u ^ (row&7))<<4)
__device__ __align__(1024) __half g_Xe[(size_t)NCHUNK * M_DIM * 64];
__device__ __align__(1024) __half g_We[(size_t)NCHUNK * N_DIM * 64];
__device__ int g_ready[NGROUP];            // per-group prep completion counters

__global__ void init_ready() {
    if (threadIdx.x < NGROUP) g_ready[threadIdx.x] = 0;
}

// ---------------------------------------------------------------------------
// Per-unit prep helpers (shared by fused + fallback paths)
// ---------------------------------------------------------------------------
__device__ __forceinline__ void prep_a_unit(const float* __restrict__ x,
                                            int c, int row, int u) {
    int k0 = c * CH_K + u * 8;
    const float* src = x + (size_t)row * K_DIM + (k0 < K_DIM ? k0 : k0 - NOUT);
    float4 v0 = *(const float4*)src;
    float4 v1 = *(const float4*)(src + 4);
    __half2 h[4];
    h[0] = __floats2half2_rn(v0.x, v0.y);
    h[1] = __floats2half2_rn(v0.z, v0.w);
    h[2] = __floats2half2_rn(v1.x, v1.y);
    h[3] = __floats2half2_rn(v1.z, v1.w);
    char* dst = (char*)g_Xe + ((size_t)c * M_DIM + row) * 128 + ((u ^ (row & 7)) << 4);
    *(uint4*)dst = *(uint4*)h;
}

__device__ __forceinline__ void prep_b_unit(const int* __restrict__ qw,
                                            const float* __restrict__ scales,
                                            const float* __restrict__ zeros,
                                            const float* __restrict__ ow,
                                            int c, int row, int u) {
    int k0 = c * CH_K + u * 8;
    __half2 h[4];
    if (k0 < K_DIM) {
        const int* qp = qw + (size_t)row * K_DIM + k0;
        int4 q0 = *(const int4*)qp;
        int4 q1 = *(const int4*)(qp + 4);
        int g = k0 >> 7;
        float s = scales[g * N_DIM + row];
        float z = zeros[g * N_DIM + row];
        h[0] = __floats2half2_rn((float)q0.x * s + z, (float)q0.y * s + z);
        h[1] = __floats2half2_rn((float)q0.z * s + z, (float)q0.w * s + z);
        h[2] = __floats2half2_rn((float)q1.x * s + z, (float)q1.y * s + z);
        h[3] = __floats2half2_rn((float)q1.z * s + z, (float)q1.w * s + z);
    } else {
        const float* op = ow + (size_t)row * NOUT + (k0 - K_DIM);
        float4 o0 = *(const float4*)op;
        float4 o1 = *(const float4*)(op + 4);
        h[0] = __floats2half2_rn(o0.x, o0.y);
        h[1] = __floats2half2_rn(o0.z, o0.w);
        h[2] = __floats2half2_rn(o1.x, o1.y);
        h[3] = __floats2half2_rn(o1.z, o1.w);
    }
    char* dst = (char*)g_We + ((size_t)c * N_DIM + row) * 128 + ((u ^ (row & 7)) << 4);
    *(uint4*)dst = *(uint4*)h;
}

// ---------------------------------------------------------------------------
// Standalone prep (FALLBACK path only)
// ---------------------------------------------------------------------------
__global__ void prep_all(const float* __restrict__ x, const int* __restrict__ qw,
                         const float* __restrict__ scales,
                         const float* __restrict__ zeros,
                         const float* __restrict__ ow) {
    int idx = blockIdx.x * blockDim.x + threadIdx.x;
    if (idx < A_UNITS) {
        int c = idx >> 16;
        int r = idx & 65535;
        prep_a_unit(x, c, r >> 3, r & 7);
    } else {
        idx -= A_UNITS;
        int c = idx >> 15;
        int r = idx & 32767;
        prep_b_unit(qw, scales, zeros, ow, c, r >> 3, r & 7);
    }
}

// ===========================================================================
// Fused persistent cg2 tcgen05 GEMM: warps 3-7 prep (batched, group-ordered),
// producer gated on ready flags for tile 0; R14 pipeline otherwise.
// ===========================================================================
#if HAS_TCGEN05
__device__ __forceinline__ uint32_t smem_u32(const void* p) {
    return (uint32_t)__cvta_generic_to_shared(p);
}
__device__ __forceinline__ uint32_t elect_one() {
    uint32_t pred;
    asm volatile("{.reg .pred p; elect.sync _|p, 0xFFFFFFFF; selp.b32 %0, 1, 0, p;}"
                 : "=r"(pred));
    return pred;
}
__device__ __forceinline__ void mma_f16_ss_cg2(uint32_t d, uint64_t ad, uint64_t bd,
                                               uint32_t idesc, uint32_t accum) {
    asm volatile(
        "{.reg .pred p; setp.ne.u32 p, %5, 0;\n\t"
        "tcgen05.mma.cta_group::2.kind::f16 [%0], %1, %2, %3, "
        "{%4,%4,%4,%4,%4,%4,%4,%4}, p;}\n"
        :: "r"(d), "l"(ad), "l"(bd), "r"(idesc), "r"(0u), "r"(accum) : "memory");
}
__device__ __forceinline__ void mbar_wait(uint32_t addr, uint32_t parity) {
    asm volatile(
        "{.reg .pred P1;\n\t"
        "LAB_WAIT_%=:\n\t"
        "mbarrier.try_wait.parity.acquire.cta.shared::cta.b64 P1, [%0], %1, 0x989680;\n\t"
        "@P1 bra LAB_DONE_%=;\n\t"
        "bra LAB_WAIT_%=;\n\t"
        "LAB_DONE_%=:}\n"
        :: "r"(addr), "r"(parity) : "memory");
}
__device__ __forceinline__ void mbar_arrive_rank0(uint32_t addr) {
    asm volatile(
        "{.reg .b32 remAddr;\n\t"
        "mapa.shared::cluster.u32 remAddr, %0, 0;\n\t"
        "mbarrier.arrive.shared::cluster.b64 _, [remAddr];}\n"
        :: "r"(addr) : "memory");
}
#endif

extern __shared__ __align__(1024) char smn[];

__global__ void __launch_bounds__(256, 1) __cluster_dims__(2, 1, 1)
gemm_persist(const float* __restrict__ x, const int* __restrict__ qw,
             const float* __restrict__ scales, const float* __restrict__ zeros,
             const float* __restrict__ ow, const float* __restrict__ bias,
             float* __restrict__ y) {
#if HAS_TCGEN05
    const int tid  = threadIdx.x;
    const int w    = tid >> 5;
    const int lane = tid & 31;
    const int bid  = blockIdx.x;                       // 0..147 (prep slice key)
    const int pid  = bid >> 1;                         // pair id 0..73
    uint32_t rank;
    asm("mov.u32 %0, %%cluster_ctarank;" : "=r"(rank));
    const int niters = (NTILE2 - 1 - pid) / NPAIR + 1; // 7 for pid<68 else 6

    const uint32_t sbase    = smem_u32(smn);
    const uint32_t ctrl     = sbase + CTRL_OFF;
    const uint32_t mb_full  = ctrl + 8;                // 6: local chunk loaded (tx)
    const uint32_t mb_pair  = ctrl + 56;               // 6: leader, count 2
    const uint32_t mb_empt  = ctrl + 104;              // 6: buffer free (count 1)
    const uint32_t mb_done  = ctrl + 152;              // 2: tile MMA done (count 1)
    const uint32_t mb_pfree = ctrl + 168;              // 2: leader, count 8 (epi warps)

    if (w == 0) {
        asm volatile("tcgen05.alloc.cta_group::2.sync.aligned.shared::cta.b32 [%0], %1;"
                     :: "r"(ctrl), "r"(512u) : "memory");
        asm volatile("tcgen05.relinquish_alloc_permit.cta_group::2.sync.aligned;");
    }
    if (tid == 0) {
#pragma unroll
        for (int s = 0; s < NSTAGE; s++) {
            asm volatile("mbarrier.init.shared.b64 [%0], 1;" :: "r"(mb_full + 8 * s) : "memory");
            asm volatile("mbarrier.init.shared.b64 [%0], 2;" :: "r"(mb_pair + 8 * s) : "memory");
            asm volatile("mbarrier.init.shared.b64 [%0], 1;" :: "r"(mb_empt + 8 * s) : "memory");
        }
#pragma unroll
        for (int b = 0; b < 2; b++) {
            asm volatile("mbarrier.init.shared.b64 [%0], 1;" :: "r"(mb_done + 8 * b)  : "memory");
            asm volatile("mbarrier.init.shared.b64 [%0], 8;" :: "r"(mb_pfree + 8 * b) : "memory");
        }
    }
    __syncthreads();
    asm volatile("barrier.cluster.arrive.aligned;" ::: "memory");
    asm volatile("barrier.cluster.wait.aligned;" ::: "memory");

    uint32_t tmem;
    asm volatile("ld.shared.b32 %0, [%1];" : "=r"(tmem) : "r"(ctrl));

    if (w == 0) {
        // ---------------- Leader MMA warp (rank 0 only) -------------------
        if (rank == 0 && elect_one()) {
            asm volatile("tcgen05.fence::after_thread_sync;" ::: "memory");
            int s = 0, ph = 0;
            for (int i = 0; i < niters; i++) {
                if (i >= 2) mbar_wait(mb_pfree + 8 * (i & 1), (uint32_t)(((i - 2) >> 1) & 1));
                const uint32_t d = tmem + (uint32_t)((i & 1) * 256);
                for (int c = 0; c < NCHUNK; c++) {
                    mbar_wait(mb_pair + 8 * s, (uint32_t)(ph & 1));
                    const uint32_t aAddr = sbase + s * STG_BYTES;
                    const uint64_t ad = DESC_BASE | ((aAddr >> 4) & 0x3FFF);
                    const uint64_t bd = DESC_BASE | (((aAddr + A_STG_BYTES) >> 4) & 0x3FFF);
#pragma unroll
                    for (int kk = 0; kk < 4; kk++)
                        mma_f16_ss_cg2(d, ad + kk * 2, bd + kk * 2, IDESC,
                                       (c > 0 || kk > 0) ? 1u : 0u);
                    asm volatile(
                        "tcgen05.commit.cta_group::2.mbarrier::arrive::one.shared::cluster"
                        ".multicast::cluster.b64 [%0], %1;"
                        :: "r"(mb_empt + 8 * s), "h"((uint16_t)0x3) : "memory");
                    if (++s == NSTAGE) { s = 0; ph++; }
                }
                asm volatile(
                    "tcgen05.commit.cta_group::2.mbarrier::arrive::one.shared::cluster"
                    ".multicast::cluster.b64 [%0], %1;"
                    :: "r"(mb_done + 8 * (i & 1)), "h"((uint16_t)0x3) : "memory");
            }
        }
    } else if (w == 1) {
        // ---------------- Producer warp (gated on prep readiness, tile 0) -
        if (elect_one()) {
            int s = 0, ph = 0;
            for (int i = 0; i < niters; i++) {
                const int tile = pid + NPAIR * i;
                const int bm = ((tile >> 4) << 8) + (int)rank * TM;
                const int bn = (tile & 15) << 8;
                for (int c = 0; c < NCHUNK; c++) {
                    if (i == 0 && (c & 1) == 0) {      // chip-wide prep gate
                        while (atomicAdd(&g_ready[c >> 1], 0) < NCTA) {}
                        __threadfence();
                        asm volatile("fence.proxy.async;" ::: "memory");
                    }
                    if (ph > 0)
                        mbar_wait(mb_empt + 8 * s, (uint32_t)((ph - 1) & 1));
                    asm volatile("mbarrier.arrive.expect_tx.shared.b64 _, [%0], %1;"
                                 :: "r"(mb_full + 8 * s), "r"((uint32_t)STG_BYTES) : "memory");
                    const uint32_t dstA = sbase + s * STG_BYTES;
                    const char* srcA = (const char*)g_Xe + ((size_t)c * M_DIM + bm) * 128;
                    asm volatile(
                        "cp.async.bulk.shared::cluster.global.mbarrier::complete_tx::bytes "
                        "[%0], [%1], %2, [%3];"
                        :: "r"(dstA), "l"(srcA), "r"((uint32_t)A_STG_BYTES),
                           "r"(mb_full + 8 * s) : "memory");
                    const char* srcB = (const char*)g_We +
                                       ((size_t)c * N_DIM + bn + (int)rank * (TN / 2)) * 128;
                    asm volatile(
                        "cp.async.bulk.shared::cluster.global.mbarrier::complete_tx::bytes "
                        "[%0], [%1], %2, [%3];"
                        :: "r"(dstA + A_STG_BYTES), "l"(srcB), "r"((uint32_t)B_STG_BYTES),
                           "r"(mb_full + 8 * s) : "memory");
                    if (++s == NSTAGE) { s = 0; ph++; }
                }
            }
        }
    } else if (w == 2) {
        // ---------------- Full-relay: local full -> leader pair-full -----
        if (elect_one()) {
            int s = 0, ph = 0;
            for (int i = 0; i < niters; i++)
                for (int c = 0; c < NCHUNK; c++) {
                    mbar_wait(mb_full + 8 * s, (uint32_t)(ph & 1));
                    mbar_arrive_rank0(mb_pair + 8 * s);
                    if (++s == NSTAGE) { s = 0; ph++; }
                }
        }
    } else {
        // ---------------- Warps 3-7: prep phase (160 threads, batched) ----
        {
            const int pt = tid - 96;                   // 0..159
            for (int g = 0; g < NGROUP; g++) {
#pragma unroll
                for (int j = 0; j < 9; j++) {
                    int idx = pt + j * 160;
                    if (idx < 1344) {                  // 2 chunks x (448 A + 224 B)
                        int c = 2 * g + (idx >= 672 ? 1 : 0);
                        int r = idx % 672;
                        if (r < 448) {
                            int row = bid * 56 + (r >> 3);
                            if (row < M_DIM) prep_a_unit(x, c, row, r & 7);
                        } else {
                            int r2 = r - 448;
                            int row = bid * 28 + (r2 >> 3);
                            if (row < N_DIM)
                                prep_b_unit(qw, scales, zeros, ow, c, row, r2 & 7);
                        }
                    }
                }
                __threadfence();                       // publish stores (gpu scope)
                asm volatile("bar.sync 2, 160;" ::: "memory");
                if (pt == 0) atomicAdd(&g_ready[g], 1);
            }
        }

        // ---------------- Warps 4-7: epilogue (drain own TMEM half) -------
        if (w >= 4) {
            const uint32_t warp_off = (uint32_t)((tid & 127) >> 5) << 21;
            const int ew = w - 4;
            for (int i = 0; i < niters; i++) {
                mbar_wait(mb_done + 8 * (i & 1), (uint32_t)((i >> 1) & 1));
                asm volatile("tcgen05.fence::after_thread_sync;" ::: "memory");
                const int tile = pid + NPAIR * i;
                const int bm = ((tile >> 4) << 8) + (int)rank * TM;
                const int bn = (tile & 15) << 8;
                const int m  = bm + (ew << 5) + lane;
                float* yrow = y + (size_t)m * N_DIM;
                const uint32_t dBase = tmem + (uint32_t)((i & 1) * 256) + warp_off;
#pragma unroll
                for (int cb = 0; cb < TN; cb += 32) {
                    uint32_t r[32];
                    asm volatile(
                        "tcgen05.ld.sync.aligned.32x32b.x32.b32 "
                        "{%0,%1,%2,%3,%4,%5,%6,%7,%8,%9,%10,%11,%12,%13,%14,%15,"
                        "%16,%17,%18,%19,%20,%21,%22,%23,%24,%25,%26,%27,%28,%29,%30,%31}, [%32];"
                        : "=r"(r[0]), "=r"(r[1]), "=r"(r[2]), "=r"(r[3]), "=r"(r[4]),
                          "=r"(r[5]), "=r"(r[6]), "=r"(r[7]), "=r"(r[8]), "=r"(r[9]),
                          "=r"(r[10]), "=r"(r[11]), "=r"(r[12]), "=r"(r[13]), "=r"(r[14]),
                          "=r"(r[15]), "=r"(r[16]), "=r"(r[17]), "=r"(r[18]), "=r"(r[19]),
                          "=r"(r[20]), "=r"(r[21]), "=r"(r[22]), "=r"(r[23]), "=r"(r[24]),
                          "=r"(r[25]), "=r"(r[26]), "=r"(r[27]), "=r"(r[28]), "=r"(r[29]),
                          "=r"(r[30]), "=r"(r[31])
                        : "r"(dBase + (uint32_t)cb));
                    asm volatile("tcgen05.wait::ld.sync.aligned;" ::: "memory");
                    const int col0 = bn + cb;
#pragma unroll
                    for (int q = 0; q < 8; q++) {
                        float4 bv = *(const float4*)(bias + col0 + q * 4);
                        float4 o;
                        o.x = __uint_as_float(r[q * 4 + 0]) + bv.x;
                        o.y = __uint_as_float(r[q * 4 + 1]) + bv.y;
                        o.z = __uint_as_float(r[q * 4 + 2]) + bv.z;
                        o.w = __uint_as_float(r[q * 4 + 3]) + bv.w;
                        *(float4*)(yrow + col0 + q * 4) = o;
                    }
                }
                asm volatile("tcgen05.fence::before_thread_sync;" ::: "memory");
                if (elect_one())
                    mbar_arrive_rank0(mb_pfree + 8 * (i & 1));   // count 8 total
            }
        }
    }

    __syncthreads();
    if (w == 0) {
        asm volatile("tcgen05.dealloc.cta_group::2.sync.aligned.b32 %0, %1;"
                     :: "r"(tmem), "r"(512u));
    }
    asm volatile("barrier.cluster.arrive.aligned;" ::: "memory");
    asm volatile("barrier.cluster.wait.aligned;" ::: "memory");
#endif  // HAS_TCGEN05
}

// ===========================================================================
// Fallback: mma.sync (compiled only when tcgen05 is unavailable); reads the
// tiled pre-swizzled gmem layout produced by prep_all.
// ===========================================================================
__global__ __launch_bounds__(256, 2) void gemm_f16(const float* __restrict__ bias,
                                                   float* __restrict__ y) {
#if !HAS_TCGEN05
    __shared__ __align__(16) __half As[3][128 * 32];
    __shared__ __align__(16) __half Bs[3][128 * 32];

    const int t    = threadIdx.x;
    const int lane = t & 31;
    const int w    = t >> 5;
    const int bm   = blockIdx.y << 7;
    const int bn   = blockIdx.x << 7;
    const int wm   = (w >> 2) << 6;
    const int wn   = (w & 3) << 5;

    const int lr = t >> 2;
    const int lc = t & 3;

    float acc[4][4][4];
#pragma unroll
    for (int i = 0; i < 4; i++)
#pragma unroll
        for (int j = 0; j < 4; j++)
#pragma unroll
            for (int r = 0; r < 4; r++) acc[i][j][r] = 0.f;

    unsigned sA = (unsigned)__cvta_generic_to_shared(As);
    unsigned sB = (unsigned)__cvta_generic_to_shared(Bs);

    auto swz = [](int row, int chunk) {
        return (row << 5) + ((chunk ^ ((row >> 1) & 3)) << 3);
    };
    auto gaddr = [](const __half* base, int rows_total, int grow, int ks, int u4) {
        int c  = ks >> 1;
        int cu = ((ks & 1) << 2) + u4;
        return (const char*)base + ((size_t)c * rows_total + grow) * 128 +
               ((cu ^ (grow & 7)) << 4);
    };

    auto load_stage = [&](int buf, int ks) {
#pragma unroll
        for (int i = 0; i < 2; i++) {
            int row = lr + (i << 6);
            unsigned da = sA + (unsigned)((buf * 4096 + swz(row, lc)) << 1);
            const char* ga = gaddr(g_Xe, M_DIM, bm + row, ks, lc);
            asm volatile("cp.async.cg.shared.global [%0], [%1], 16;\n" ::"r"(da), "l"(ga));
            unsigned db = sB + (unsigned)((buf * 4096 + swz(row, lc)) << 1);
            const char* gb = gaddr(g_We, N_DIM, bn + row, ks, lc);
            asm volatile("cp.async.cg.shared.global [%0], [%1], 16;\n" ::"r"(db), "l"(gb));
        }
    };

    const int NSTEP = KE / 32;
    load_stage(0, 0);
    asm volatile("cp.async.commit_group;\n");
    load_stage(1, 1);
    asm volatile("cp.async.commit_group;\n");

    const int a_row  = wm + (lane & 15);
    const int a_cofs = lane >> 4;
    const int b_row  = wn + (lane & 7) + ((lane >> 4) << 3);
    const int b_cofs = (lane >> 3) & 1;

    for (int ks = 0; ks < NSTEP; ks++) {
        asm volatile("cp.async.wait_group 1;\n");
        __syncthreads();
        int buf = ks % 3;
        if (ks + 2 < NSTEP) load_stage((ks + 2) % 3, ks + 2);
        asm volatile("cp.async.commit_group;\n");

        unsigned baseA = sA + (unsigned)(buf * 8192);
        unsigned baseB = sB + (unsigned)(buf * 8192);

#pragma unroll
        for (int p = 0; p < 2; p++) {
            unsigned a[4][4];
#pragma unroll
            for (int i = 0; i < 4; i++) {
                int row = a_row + (i << 4);
                int chunk = (p << 1) + a_cofs;
                unsigned addr = baseA + (unsigned)(swz(row, chunk) << 1);
                asm volatile(
                    "ldmatrix.sync.aligned.m8n8.x4.shared.b16 {%0,%1,%2,%3}, [%4];\n"
                    : "=r"(a[i][0]), "=r"(a[i][1]), "=r"(a[i][2]), "=r"(a[i][3])
                    : "r"(addr));
            }
            unsigned b[4][2];
#pragma unroll
            for (int jj = 0; jj < 2; jj++) {
                int row = b_row + (jj << 4);
                int chunk = (p << 1) + b_cofs;
                unsigned addr = baseB + (unsigned)(swz(row, chunk) << 1);
                unsigned r0, r1, r2, r3;
                asm volatile(
                    "ldmatrix.sync.aligned.m8n8.x4.shared.b16 {%0,%1,%2,%3}, [%4];\n"
                    : "=r"(r0), "=r"(r1), "=r"(r2), "=r"(r3)
                    : "r"(addr));
                b[jj * 2][0] = r0; b[jj * 2][1] = r1;
                b[jj * 2 + 1][0] = r2; b[jj * 2 + 1][1] = r3;
            }
#pragma unroll
            for (int i = 0; i < 4; i++)
#pragma unroll
                for (int j = 0; j < 4; j++)
                    asm volatile(
                        "mma.sync.aligned.m16n8k16.row.col.f32.f16.f16.f32 "
                        "{%0,%1,%2,%3}, {%4,%5,%6,%7}, {%8,%9}, {%0,%1,%2,%3};\n"
                        : "+f"(acc[i][j][0]), "+f"(acc[i][j][1]),
                          "+f"(acc[i][j][2]), "+f"(acc[i][j][3])
                        : "r"(a[i][0]), "r"(a[i][1]), "r"(a[i][2]), "r"(a[i][3]),
                          "r"(b[j][0]), "r"(b[j][1]));
        }
    }

#pragma unroll
    for (int i = 0; i < 4; i++) {
        int row = bm + wm + (i << 4) + (lane >> 2);
#pragma unroll
        for (int j = 0; j < 4; j++) {
            int col = bn + wn + (j << 3) + ((lane & 3) << 1);
            float2 bb = *(const float2*)(bias + col);
            float2 o0 = make_float2(acc[i][j][0] + bb.x, acc[i][j][1] + bb.y);
            float2 o1 = make_float2(acc[i][j][2] + bb.x, acc[i][j][3] + bb.y);
            *(float2*)(y + (size_t)row * N_DIM + col)       = o0;
            *(float2*)(y + (size_t)(row + 8) * N_DIM + col) = o1;
        }
    }
#endif  // !HAS_TCGEN05
}

// ---------------------------------------------------------------------------
extern "C" void kernel_launch(void* const* d_in, const int* in_sizes, int n_in,
                              void* d_out, int out_size) {
    const float* x      = (const float*)d_in[0];
    const int*   qw     = (const int*)d_in[1];
    const float* scales = (const float*)d_in[2];
    const float* zeros  = (const float*)d_in[3];
    const float* ow     = (const float*)d_in[4];
    const float* bias   = (const float*)d_in[5];
    float*       y      = (float*)d_out;

    // Exactly one GEMM kernel has a real body (decided at device-compile time);
    // the real one is the one with more registers. Pure host query, capture-safe.
    cudaFuncAttributes aT{}, aF{};
    cudaFuncGetAttributes(&aT, gemm_persist);
    cudaFuncGetAttributes(&aF, gemm_f16);

    if (aT.numRegs >= aF.numRegs) {
        // Fused path: prep happens inside the persistent kernel.
        init_ready<<<1, 64>>>();
        cudaFuncSetAttribute(gemm_persist, cudaFuncAttributeMaxDynamicSharedMemorySize,
                             SMEM_TOTAL);
        gemm_persist<<<NCTA, 256, SMEM_TOTAL>>>(x, qw, scales, zeros, ow, bias, y);
    } else {
        prep_all<<<PREP_THREADS, 256>>>(x, qw, scales, zeros, ow);
        dim3 gridF(N_DIM / 128, M_DIM / 128);
        gemm_f16<<<gridF, 256>>>(bias, y);
    }
}

// round 16
// speedup vs baseline: 1.5182x; 1.5182x over previous
#include <cuda_runtime.h>
#include <cuda_fp16.h>
#include <cstdint>

// ===========================================================================
// Arch-feature detection: tcgen05 exists only on 'a'/'f' feature targets.
// ===========================================================================
#define HAS_TCGEN05 0
#if defined(__CUDA_ARCH__) && (__CUDA_ARCH__ >= 1000)
#  if defined(__CUDA_ARCH_FAMILY_SPECIFIC__) || defined(__CUDA_ARCH_SPECIFIC__)
#    undef HAS_TCGEN05
#    define HAS_TCGEN05 1
#  elif defined(__CUDA_ARCH_HAS_FEATURE__)
#    if __CUDA_ARCH_HAS_FEATURE__(SM103_ALL) || __CUDA_ARCH_HAS_FEATURE__(SM100_ALL)
#      undef HAS_TCGEN05
#      define HAS_TCGEN05 1
#    endif
#  endif
#endif

// Problem constants
#define M_DIM 8192
#define N_DIM 4096
#define K_DIM 4096
#define NOUT  128
#define KE    4224            // K + NOUT (outlier GEMM fused as extra K)

// cg2 persistent tiling: 74 pairs, 256x256 pair tiles; 32x16 = 512 tiles
#define TM 128                // A rows per CTA (pair covers 256)
#define TN 256                // N per pair tile (each CTA loads TN/2 B rows)
#define CH_K 64               // K-halves per scratch block (layout granule)
#define NCHUNK (KE / CH_K)    // 66 blocks
#define NSTEP2 (NCHUNK / 2)   // 33 pipeline steps (K128 each)
#define NSTAGE 3
#define NCTA 148
#define NPAIR 74
#define NTILE2 512
#define BLK_BYTES   (TM * 128)            // 16384 per K64 block (A or B half)
#define STG_BYTES   (4 * BLK_BYTES)       // 65536: A(2 blocks) + B(2 blocks)
#define CTRL_OFF    (NSTAGE * STG_BYTES)  // 196608
#define SMEM_TOTAL  (CTRL_OFF + 256)

// idesc kind::f16 cg2: dtype=F32(1<<4), N=256 -> 32<<17, M=256 -> 16<<24
#define IDESC ((1u << 4) | ((TN / 8) << 17) | (16u << 24))
#define DESC_BASE ((uint64_t(2) << 61) | (uint64_t(1) << 46) | (uint64_t(64) << 32) | (uint64_t(1) << 16))

// Prep work partition (one merged kernel)
#define A_UNITS (NCHUNK * M_DIM * 8)      // 4,325,376
#define B_UNITS (NCHUNK * N_DIM * 8)      // 2,162,688
#define PREP_THREADS ((A_UNITS + B_UNITS) / 256)

// Scratch fp16 operands in BLOCK-MAJOR, PRE-SWIZZLED (SW128) layout:
//   byte addr of 16B unit (c, row, u) = ((c*ROWS + row)*128) + ((u ^ (row&7))<<4)
__device__ __align__(1024) __half g_Xe[(size_t)NCHUNK * M_DIM * 64];
__device__ __align__(1024) __half g_We[(size_t)NCHUNK * N_DIM * 64];

// ---------------------------------------------------------------------------
// Merged prep: fp32->fp16 X (+outlier dup) AND dequant W in ONE launch.
// ---------------------------------------------------------------------------
__global__ void prep_all(const float* __restrict__ x, const int* __restrict__ qw,
                         const float* __restrict__ scales,
                         const float* __restrict__ zeros,
                         const float* __restrict__ ow) {
    int idx = blockIdx.x * blockDim.x + threadIdx.x;
    if (idx < A_UNITS) {
        int c  = idx >> 16;
        int r  = idx & 65535;
        int m  = r >> 3;
        int u  = r & 7;
        int k0 = c * CH_K + u * 8;
        const float* src = x + (size_t)m * K_DIM + (k0 < K_DIM ? k0 : k0 - NOUT);
        float4 v0 = *(const float4*)src;
        float4 v1 = *(const float4*)(src + 4);
        __half2 h[4];
        h[0] = __floats2half2_rn(v0.x, v0.y);
        h[1] = __floats2half2_rn(v0.z, v0.w);
        h[2] = __floats2half2_rn(v1.x, v1.y);
        h[3] = __floats2half2_rn(v1.z, v1.w);
        char* dst = (char*)g_Xe + ((size_t)c * M_DIM + m) * 128 + ((u ^ (m & 7)) << 4);
        *(uint4*)dst = *(uint4*)h;
    } else {
        idx -= A_UNITS;
        int c  = idx >> 15;
        int r  = idx & 32767;
        int n  = r >> 3;
        int u  = r & 7;
        int k0 = c * CH_K + u * 8;
        __half2 h[4];
        if (k0 < K_DIM) {
            const int* qp = qw + (size_t)n * K_DIM + k0;
            int4 q0 = *(const int4*)qp;
            int4 q1 = *(const int4*)(qp + 4);
            int g = k0 >> 7;
            float s = scales[g * N_DIM + n];
            float z = zeros[g * N_DIM + n];
            h[0] = __floats2half2_rn((float)q0.x * s + z, (float)q0.y * s + z);
            h[1] = __floats2half2_rn((float)q0.z * s + z, (float)q0.w * s + z);
            h[2] = __floats2half2_rn((float)q1.x * s + z, (float)q1.y * s + z);
            h[3] = __floats2half2_rn((float)q1.z * s + z, (float)q1.w * s + z);
        } else {
            const float* op = ow + (size_t)n * NOUT + (k0 - K_DIM);
            float4 o0 = *(const float4*)op;
            float4 o1 = *(const float4*)(op + 4);
            h[0] = __floats2half2_rn(o0.x, o0.y);
            h[1] = __floats2half2_rn(o0.z, o0.w);
            h[2] = __floats2half2_rn(o1.x, o1.y);
            h[3] = __floats2half2_rn(o1.z, o1.w);
        }
        char* dst = (char*)g_We + ((size_t)c * N_DIM + n) * 128 + ((u ^ (n & 7)) << 4);
        *(uint4*)dst = *(uint4*)h;
    }
}

// ===========================================================================
// Persistent cg2 tcgen05 GEMM — R14 topology, K128 pipeline steps (3 stages).
// ===========================================================================
#if HAS_TCGEN05
__device__ __forceinline__ uint32_t smem_u32(const void* p) {
    return (uint32_t)__cvta_generic_to_shared(p);
}
__device__ __forceinline__ uint32_t elect_one() {
    uint32_t pred;
    asm volatile("{.reg .pred p; elect.sync _|p, 0xFFFFFFFF; selp.b32 %0, 1, 0, p;}"
                 : "=r"(pred));
    return pred;
}
__device__ __forceinline__ void mma_f16_ss_cg2(uint32_t d, uint64_t ad, uint64_t bd,
                                               uint32_t idesc, uint32_t accum) {
    asm volatile(
        "{.reg .pred p; setp.ne.u32 p, %5, 0;\n\t"
        "tcgen05.mma.cta_group::2.kind::f16 [%0], %1, %2, %3, "
        "{%4,%4,%4,%4,%4,%4,%4,%4}, p;}\n"
        :: "r"(d), "l"(ad), "l"(bd), "r"(idesc), "r"(0u), "r"(accum) : "memory");
}
__device__ __forceinline__ void mbar_wait(uint32_t addr, uint32_t parity) {
    asm volatile(
        "{.reg .pred P1;\n\t"
        "LAB_WAIT_%=:\n\t"
        "mbarrier.try_wait.parity.acquire.cta.shared::cta.b64 P1, [%0], %1, 0x989680;\n\t"
        "@P1 bra LAB_DONE_%=;\n\t"
        "bra LAB_WAIT_%=;\n\t"
        "LAB_DONE_%=:}\n"
        :: "r"(addr), "r"(parity) : "memory");
}
__device__ __forceinline__ void mbar_arrive_rank0(uint32_t addr) {
    asm volatile(
        "{.reg .b32 remAddr;\n\t"
        "mapa.shared::cluster.u32 remAddr, %0, 0;\n\t"
        "mbarrier.arrive.shared::cluster.b64 _, [remAddr];}\n"
        :: "r"(addr) : "memory");
}
#endif

extern __shared__ __align__(1024) char smn[];

__global__ void __launch_bounds__(256, 1) __cluster_dims__(2, 1, 1)
gemm_persist(const float* __restrict__ bias, float* __restrict__ y) {
#if HAS_TCGEN05
    const int tid  = threadIdx.x;
    const int w    = tid >> 5;
    const int lane = tid & 31;
    const int pid  = blockIdx.x >> 1;                  // pair id 0..73
    uint32_t rank;
    asm("mov.u32 %0, %%cluster_ctarank;" : "=r"(rank));
    const int niters = (NTILE2 - 1 - pid) / NPAIR + 1; // 7 for pid<68 else 6

    const uint32_t sbase    = smem_u32(smn);
    const uint32_t ctrl     = sbase + CTRL_OFF;
    const uint32_t mb_full  = ctrl + 8;                // 3: local step loaded (tx)
    const uint32_t mb_pair  = ctrl + 32;               // 3: leader, count 2
    const uint32_t mb_empt  = ctrl + 56;               // 3: buffer free (count 1)
    const uint32_t mb_done  = ctrl + 80;               // 2: tile MMA done (count 1)
    const uint32_t mb_lfree = ctrl + 96;               // 2: local epi done (count 128)
    const uint32_t mb_pfree = ctrl + 112;              // 2: leader, count 2

    if (w == 0) {
        asm volatile("tcgen05.alloc.cta_group::2.sync.aligned.shared::cta.b32 [%0], %1;"
                     :: "r"(ctrl), "r"(512u) : "memory");
        asm volatile("tcgen05.relinquish_alloc_permit.cta_group::2.sync.aligned;");
    }
    if (tid == 0) {
#pragma unroll
        for (int s = 0; s < NSTAGE; s++) {
            asm volatile("mbarrier.init.shared.b64 [%0], 1;" :: "r"(mb_full + 8 * s) : "memory");
            asm volatile("mbarrier.init.shared.b64 [%0], 2;" :: "r"(mb_pair + 8 * s) : "memory");
            asm volatile("mbarrier.init.shared.b64 [%0], 1;" :: "r"(mb_empt + 8 * s) : "memory");
        }
#pragma unroll
        for (int b = 0; b < 2; b++) {
            asm volatile("mbarrier.init.shared.b64 [%0], 1;"   :: "r"(mb_done + 8 * b)  : "memory");
            asm volatile("mbarrier.init.shared.b64 [%0], 128;" :: "r"(mb_lfree + 8 * b) : "memory");
            asm volatile("mbarrier.init.shared.b64 [%0], 2;"   :: "r"(mb_pfree + 8 * b) : "memory");
        }
    }
    __syncthreads();
    // All cluster mbarriers visible before any cross-CTA arrive/commit.
    asm volatile("barrier.cluster.arrive.aligned;" ::: "memory");
    asm volatile("barrier.cluster.wait.aligned;" ::: "memory");

    uint32_t tmem;
    asm volatile("ld.shared.b32 %0, [%1];" : "=r"(tmem) : "r"(ctrl));

    if (w == 0) {
        // ---------------- Leader MMA warp (rank 0 only) -------------------
        if (rank == 0 && elect_one()) {
            asm volatile("tcgen05.fence::after_thread_sync;" ::: "memory");
            int s = 0, ph = 0;
            for (int i = 0; i < niters; i++) {
                if (i >= 2) mbar_wait(mb_pfree + 8 * (i & 1), (uint32_t)(((i - 2) >> 1) & 1));
                const uint32_t d = tmem + (uint32_t)((i & 1) * 256);
                for (int c = 0; c < NSTEP2; c++) {
                    mbar_wait(mb_pair + 8 * s, (uint32_t)(ph & 1));
                    const uint32_t stg = sbase + s * STG_BYTES;
#pragma unroll
                    for (int kb = 0; kb < 2; kb++) {   // two K64 blocks per step
                        const uint64_t ad = DESC_BASE | (((stg + kb * BLK_BYTES) >> 4) & 0x3FFF);
                        const uint64_t bd = DESC_BASE |
                            (((stg + (2 + kb) * BLK_BYTES) >> 4) & 0x3FFF);
#pragma unroll
                        for (int kk = 0; kk < 4; kk++)
                            mma_f16_ss_cg2(d, ad + kk * 2, bd + kk * 2, IDESC,
                                           (c > 0 || kb > 0 || kk > 0) ? 1u : 0u);
                    }
                    // Buffer free in BOTH CTAs (MMA reads peer SMEM too).
                    asm volatile(
                        "tcgen05.commit.cta_group::2.mbarrier::arrive::one.shared::cluster"
                        ".multicast::cluster.b64 [%0], %1;"
                        :: "r"(mb_empt + 8 * s), "h"((uint16_t)0x3) : "memory");
                    if (++s == NSTAGE) { s = 0; ph++; }
                }
                // Tile done -> both CTAs drain their TMEM half.
                asm volatile(
                    "tcgen05.commit.cta_group::2.mbarrier::arrive::one.shared::cluster"
                    ".multicast::cluster.b64 [%0], %1;"
                    :: "r"(mb_done + 8 * (i & 1)), "h"((uint16_t)0x3) : "memory");
            }
        }
    } else if (w == 1) {
        // ---------------- Producer warp: 4 bulk copies per K128 step ------
        if (elect_one()) {
            int s = 0, ph = 0;
            for (int i = 0; i < niters; i++) {
                const int tile = pid + NPAIR * i;
                const int bm = ((tile >> 4) << 8) + (int)rank * TM;  // m slow
                const int bn = (tile & 15) << 8;                     // n FAST (B resident)
                for (int c = 0; c < NSTEP2; c++) {
                    if (ph > 0)
                        mbar_wait(mb_empt + 8 * s, (uint32_t)((ph - 1) & 1));
                    asm volatile("mbarrier.arrive.expect_tx.shared.b64 _, [%0], %1;"
                                 :: "r"(mb_full + 8 * s), "r"((uint32_t)STG_BYTES) : "memory");
                    const uint32_t stg = sbase + s * STG_BYTES;
#pragma unroll
                    for (int kb = 0; kb < 2; kb++) {
                        const int cb = 2 * c + kb;
                        const char* srcA = (const char*)g_Xe +
                                           ((size_t)cb * M_DIM + bm) * 128;
                        asm volatile(
                            "cp.async.bulk.shared::cluster.global.mbarrier::complete_tx::bytes "
                            "[%0], [%1], %2, [%3];"
                            :: "r"(stg + kb * BLK_BYTES), "l"(srcA),
                               "r"((uint32_t)BLK_BYTES), "r"(mb_full + 8 * s) : "memory");
                        const char* srcB = (const char*)g_We +
                                           ((size_t)cb * N_DIM + bn + (int)rank * (TN / 2)) * 128;
                        asm volatile(
                            "cp.async.bulk.shared::cluster.global.mbarrier::complete_tx::bytes "
                            "[%0], [%1], %2, [%3];"
                            :: "r"(stg + (2 + kb) * BLK_BYTES), "l"(srcB),
                               "r"((uint32_t)BLK_BYTES), "r"(mb_full + 8 * s) : "memory");
                    }
                    if (++s == NSTAGE) { s = 0; ph++; }
                }
            }
        }
    } else if (w == 2) {
        // ---------------- Full-relay: local full -> leader pair-full -----
        if (elect_one()) {
            int s = 0, ph = 0;
            for (int i = 0; i < niters; i++)
                for (int c = 0; c < NSTEP2; c++) {
                    mbar_wait(mb_full + 8 * s, (uint32_t)(ph & 1));
                    mbar_arrive_rank0(mb_pair + 8 * s);
                    if (++s == NSTAGE) { s = 0; ph++; }
                }
        }
    } else if (w == 3) {
        // ---------------- Free-relay: local epi done -> leader pair-free --
        if (elect_one()) {
            for (int i = 0; i < niters; i++) {
                mbar_wait(mb_lfree + 8 * (i & 1), (uint32_t)((i >> 1) & 1));
                mbar_arrive_rank0(mb_pfree + 8 * (i & 1));
            }
        }
    } else {
        // ---------------- Epilogue warps 4-7: drain own TMEM half --------
        const uint32_t warp_off = (uint32_t)((tid & 127) >> 5) << 21;
        const int ew = w - 4;
        for (int i = 0; i < niters; i++) {
            mbar_wait(mb_done + 8 * (i & 1), (uint32_t)((i >> 1) & 1));
            asm volatile("tcgen05.fence::after_thread_sync;" ::: "memory");
            const int tile = pid + NPAIR * i;
            const int bm = ((tile >> 4) << 8) + (int)rank * TM;
            const int bn = (tile & 15) << 8;
            const int m  = bm + (ew << 5) + lane;
            float* yrow = y + (size_t)m * N_DIM;
            const uint32_t dBase = tmem + (uint32_t)((i & 1) * 256) + warp_off;
#pragma unroll
            for (int cb = 0; cb < TN; cb += 32) {
                uint32_t r[32];
                asm volatile(
                    "tcgen05.ld.sync.aligned.32x32b.x32.b32 "
                    "{%0,%1,%2,%3,%4,%5,%6,%7,%8,%9,%10,%11,%12,%13,%14,%15,"
                    "%16,%17,%18,%19,%20,%21,%22,%23,%24,%25,%26,%27,%28,%29,%30,%31}, [%32];"
                    : "=r"(r[0]), "=r"(r[1]), "=r"(r[2]), "=r"(r[3]), "=r"(r[4]),
                      "=r"(r[5]), "=r"(r[6]), "=r"(r[7]), "=r"(r[8]), "=r"(r[9]),
                      "=r"(r[10]), "=r"(r[11]), "=r"(r[12]), "=r"(r[13]), "=r"(r[14]),
                      "=r"(r[15]), "=r"(r[16]), "=r"(r[17]), "=r"(r[18]), "=r"(r[19]),
                      "=r"(r[20]), "=r"(r[21]), "=r"(r[22]), "=r"(r[23]), "=r"(r[24]),
                      "=r"(r[25]), "=r"(r[26]), "=r"(r[27]), "=r"(r[28]), "=r"(r[29]),
                      "=r"(r[30]), "=r"(r[31])
                    : "r"(dBase + (uint32_t)cb));
                asm volatile("tcgen05.wait::ld.sync.aligned;" ::: "memory");
                const int col0 = bn + cb;
#pragma unroll
                for (int q = 0; q < 8; q++) {
                    float4 bv = *(const float4*)(bias + col0 + q * 4);
                    float4 o;
                    o.x = __uint_as_float(r[q * 4 + 0]) + bv.x;
                    o.y = __uint_as_float(r[q * 4 + 1]) + bv.y;
                    o.z = __uint_as_float(r[q * 4 + 2]) + bv.z;
                    o.w = __uint_as_float(r[q * 4 + 3]) + bv.w;
                    *(float4*)(yrow + col0 + q * 4) = o;
                }
            }
            asm volatile("tcgen05.fence::before_thread_sync;" ::: "memory");
            asm volatile("mbarrier.arrive.shared.b64 _, [%0];"
                         :: "r"(mb_lfree + 8 * (i & 1)) : "memory");
        }
    }

    __syncthreads();
    if (w == 0) {
        asm volatile("tcgen05.dealloc.cta_group::2.sync.aligned.b32 %0, %1;"
                     :: "r"(tmem), "r"(512u));
    }
    // No CTA may exit while the peer may still touch its SMEM/TMEM.
    asm volatile("barrier.cluster.arrive.aligned;" ::: "memory");
    asm volatile("barrier.cluster.wait.aligned;" ::: "memory");
#endif  // HAS_TCGEN05
}

// ===========================================================================
// Fallback: mma.sync (compiled only when tcgen05 is unavailable); reads the
// tiled pre-swizzled gmem layout produced by prep_all.
// ===========================================================================
__global__ __launch_bounds__(256, 2) void gemm_f16(const float* __restrict__ bias,
                                                   float* __restrict__ y) {
#if !HAS_TCGEN05
    __shared__ __align__(16) __half As[3][128 * 32];
    __shared__ __align__(16) __half Bs[3][128 * 32];

    const int t    = threadIdx.x;
    const int lane = t & 31;
    const int w    = t >> 5;
    const int bm   = blockIdx.y << 7;
    const int bn   = blockIdx.x << 7;
    const int wm   = (w >> 2) << 6;
    const int wn   = (w & 3) << 5;

    const int lr = t >> 2;
    const int lc = t & 3;

    float acc[4][4][4];
#pragma unroll
    for (int i = 0; i < 4; i++)
#pragma unroll
        for (int j = 0; j < 4; j++)
#pragma unroll
            for (int r = 0; r < 4; r++) acc[i][j][r] = 0.f;

    unsigned sA = (unsigned)__cvta_generic_to_shared(As);
    unsigned sB = (unsigned)__cvta_generic_to_shared(Bs);

    auto swz = [](int row, int chunk) {
        return (row << 5) + ((chunk ^ ((row >> 1) & 3)) << 3);
    };
    auto gaddr = [](const __half* base, int rows_total, int grow, int ks, int u4) {
        int c  = ks >> 1;
        int cu = ((ks & 1) << 2) + u4;
        return (const char*)base + ((size_t)c * rows_total + grow) * 128 +
               ((cu ^ (grow & 7)) << 4);
    };

    auto load_stage = [&](int buf, int ks) {
#pragma unroll
        for (int i = 0; i < 2; i++) {
            int row = lr + (i << 6);
            unsigned da = sA + (unsigned)((buf * 4096 + swz(row, lc)) << 1);
            const char* ga = gaddr(g_Xe, M_DIM, bm + row, ks, lc);
            asm volatile("cp.async.cg.shared.global [%0], [%1], 16;\n" ::"r"(da), "l"(ga));
            unsigned db = sB + (unsigned)((buf * 4096 + swz(row, lc)) << 1);
            const char* gb = gaddr(g_We, N_DIM, bn + row, ks, lc);
            asm volatile("cp.async.cg.shared.global [%0], [%1], 16;\n" ::"r"(db), "l"(gb));
        }
    };

    const int NSTEP = KE / 32;
    load_stage(0, 0);
    asm volatile("cp.async.commit_group;\n");
    load_stage(1, 1);
    asm volatile("cp.async.commit_group;\n");

    const int a_row  = wm + (lane & 15);
    const int a_cofs = lane >> 4;
    const int b_row  = wn + (lane & 7) + ((lane >> 4) << 3);
    const int b_cofs = (lane >> 3) & 1;

    for (int ks = 0; ks < NSTEP; ks++) {
        asm volatile("cp.async.wait_group 1;\n");
        __syncthreads();
        int buf = ks % 3;
        if (ks + 2 < NSTEP) load_stage((ks + 2) % 3, ks + 2);
        asm volatile("cp.async.commit_group;\n");

        unsigned baseA = sA + (unsigned)(buf * 8192);
        unsigned baseB = sB + (unsigned)(buf * 8192);

#pragma unroll
        for (int p = 0; p < 2; p++) {
            unsigned a[4][4];
#pragma unroll
            for (int i = 0; i < 4; i++) {
                int row = a_row + (i << 4);
                int chunk = (p << 1) + a_cofs;
                unsigned addr = baseA + (unsigned)(swz(row, chunk) << 1);
                asm volatile(
                    "ldmatrix.sync.aligned.m8n8.x4.shared.b16 {%0,%1,%2,%3}, [%4];\n"
                    : "=r"(a[i][0]), "=r"(a[i][1]), "=r"(a[i][2]), "=r"(a[i][3])
                    : "r"(addr));
            }
            unsigned b[4][2];
#pragma unroll
            for (int jj = 0; jj < 2; jj++) {
                int row = b_row + (jj << 4);
                int chunk = (p << 1) + b_cofs;
                unsigned addr = baseB + (unsigned)(swz(row, chunk) << 1);
                unsigned r0, r1, r2, r3;
                asm volatile(
                    "ldmatrix.sync.aligned.m8n8.x4.shared.b16 {%0,%1,%2,%3}, [%4];\n"
                    : "=r"(r0), "=r"(r1), "=r"(r2), "=r"(r3)
                    : "r"(addr));
                b[jj * 2][0] = r0; b[jj * 2][1] = r1;
                b[jj * 2 + 1][0] = r2; b[jj * 2 + 1][1] = r3;
            }
#pragma unroll
            for (int i = 0; i < 4; i++)
#pragma unroll
                for (int j = 0; j < 4; j++)
                    asm volatile(
                        "mma.sync.aligned.m16n8k16.row.col.f32.f16.f16.f32 "
                        "{%0,%1,%2,%3}, {%4,%5,%6,%7}, {%8,%9}, {%0,%1,%2,%3};\n"
                        : "+f"(acc[i][j][0]), "+f"(acc[i][j][1]),
                          "+f"(acc[i][j][2]), "+f"(acc[i][j][3])
                        : "r"(a[i][0]), "r"(a[i][1]), "r"(a[i][2]), "r"(a[i][3]),
                          "r"(b[j][0]), "r"(b[j][1]));
        }
    }

#pragma unroll
    for (int i = 0; i < 4; i++) {
        int row = bm + wm + (i << 4) + (lane >> 2);
#pragma unroll
        for (int j = 0; j < 4; j++) {
            int col = bn + wn + (j << 3) + ((lane & 3) << 1);
            float2 bb = *(const float2*)(bias + col);
            float2 o0 = make_float2(acc[i][j][0] + bb.x, acc[i][j][1] + bb.y);
            float2 o1 = make_float2(acc[i][j][2] + bb.x, acc[i][j][3] + bb.y);
            *(float2*)(y + (size_t)row * N_DIM + col)       = o0;
            *(float2*)(y + (size_t)(row + 8) * N_DIM + col) = o1;
        }
    }
#endif  // !HAS_TCGEN05
}

// ---------------------------------------------------------------------------
extern "C" void kernel_launch(void* const* d_in, const int* in_sizes, int n_in,
                              void* d_out, int out_size) {
    const float* x      = (const float*)d_in[0];
    const int*   qw     = (const int*)d_in[1];
    const float* scales = (const float*)d_in[2];
    const float* zeros  = (const float*)d_in[3];
    const float* ow     = (const float*)d_in[4];
    const float* bias   = (const float*)d_in[5];
    float*       y      = (float*)d_out;

    prep_all<<<PREP_THREADS, 256>>>(x, qw, scales, zeros, ow);

    // Exactly one GEMM kernel has a real body (decided at device-compile time);
    // the real one is the one with more registers. Pure host query, capture-safe.
    cudaFuncAttributes aT{}, aF{};
    cudaFuncGetAttributes(&aT, gemm_persist);
    cudaFuncGetAttributes(&aF, gemm_f16);

    if (aT.numRegs >= aF.numRegs) {
        cudaFuncSetAttribute(gemm_persist, cudaFuncAttributeMaxDynamicSharedMemorySize,
                             SMEM_TOTAL);
        gemm_persist<<<NCTA, 256, SMEM_TOTAL>>>(bias, y);   // 74 clusters of 2
    } else {
        dim3 gridF(N_DIM / 128, M_DIM / 128);
        gemm_f16<<<gridF, 256>>>(bias, y);
    }
}

// round 17
// speedup vs baseline: 1.5213x; 1.0021x over previous
#include <cuda_runtime.h>
#include <cuda_fp16.h>
#include <cstdint>

// ===========================================================================
// Arch-feature detection: tcgen05 exists only on 'a'/'f' feature targets.
// ===========================================================================
#define HAS_TCGEN05 0
#if defined(__CUDA_ARCH__) && (__CUDA_ARCH__ >= 1000)
#  if defined(__CUDA_ARCH_FAMILY_SPECIFIC__) || defined(__CUDA_ARCH_SPECIFIC__)
#    undef HAS_TCGEN05
#    define HAS_TCGEN05 1
#  elif defined(__CUDA_ARCH_HAS_FEATURE__)
#    if __CUDA_ARCH_HAS_FEATURE__(SM103_ALL) || __CUDA_ARCH_HAS_FEATURE__(SM100_ALL)
#      undef HAS_TCGEN05
#      define HAS_TCGEN05 1
#    endif
#  endif
#endif

// Problem constants
#define M_DIM 8192
#define N_DIM 4096
#define K_DIM 4096
#define NOUT  128
#define KE    4224            // K + NOUT (outlier GEMM fused as extra K)

// cg2 persistent tiling: 74 pairs, 256x256 pair tiles; 32x16 = 512 tiles
#define TM 128                // A rows per CTA (pair covers 256)
#define TN 256                // N per pair tile (each CTA loads TN/2 B rows)
#define CH_K 64
#define NCHUNK (KE / CH_K)    // 66
#define NSTAGE 7
#define NCTA 148
#define NPAIR 74
#define NTILE2 512
#define A_STG_BYTES (TM * 128)            // 16384
#define B_STG_BYTES ((TN / 2) * 128)      // 16384
#define STG_BYTES   (A_STG_BYTES + B_STG_BYTES)   // 32768
#define CTRL_OFF    (NSTAGE * STG_BYTES)          // 229376
#define SMEM_TOTAL  (CTRL_OFF + 256)              // 229632 (< 232448 opt-in max)

// idesc kind::f16 cg2: dtype=F32(1<<4), N=256 -> 32<<17, M=256 -> 16<<24
#define IDESC ((1u << 4) | ((TN / 8) << 17) | (16u << 24))
#define DESC_BASE ((uint64_t(2) << 61) | (uint64_t(1) << 46) | (uint64_t(64) << 32) | (uint64_t(1) << 16))

// Prep work partition (2 units per thread for MLP)
#define A_UNITS (NCHUNK * M_DIM * 8)      // 4,325,376 (even)
#define B_UNITS (NCHUNK * N_DIM * 8)      // 2,162,688 (even)
#define PREP_BLOCKS ((A_UNITS + B_UNITS) / 512)   // 12,672

// Scratch fp16 operands in CHUNK-MAJOR, PRE-SWIZZLED (SW128) layout:
//   byte addr of 16B unit (c, row, u) = ((c*ROWS + row)*128) + ((u ^ (row&7))<<4)
__device__ __align__(1024) __half g_Xe[(size_t)NCHUNK * M_DIM * 64];
__device__ __align__(1024) __half g_We[(size_t)NCHUNK * N_DIM * 64];

// ---------------------------------------------------------------------------
// Merged prep: fp32->fp16 X (+outlier dup) AND dequant W; 2 units/thread.
// ---------------------------------------------------------------------------
__global__ void prep_all(const float* __restrict__ x, const int* __restrict__ qw,
                         const float* __restrict__ scales,
                         const float* __restrict__ zeros,
                         const float* __restrict__ ow) {
    const int base = (blockIdx.x * blockDim.x + threadIdx.x) * 2;
#pragma unroll
    for (int t = 0; t < 2; t++) {
        int idx = base + t;
        if (idx < A_UNITS) {
            int c  = idx >> 16;
            int r  = idx & 65535;
            int m  = r >> 3;
            int u  = r & 7;
            int k0 = c * CH_K + u * 8;
            const float* src = x + (size_t)m * K_DIM + (k0 < K_DIM ? k0 : k0 - NOUT);
            float4 v0 = *(const float4*)src;
            float4 v1 = *(const float4*)(src + 4);
            __half2 h[4];
            h[0] = __floats2half2_rn(v0.x, v0.y);
            h[1] = __floats2half2_rn(v0.z, v0.w);
            h[2] = __floats2half2_rn(v1.x, v1.y);
            h[3] = __floats2half2_rn(v1.z, v1.w);
            char* dst = (char*)g_Xe + ((size_t)c * M_DIM + m) * 128 + ((u ^ (m & 7)) << 4);
            *(uint4*)dst = *(uint4*)h;
        } else {
            int idx2 = idx - A_UNITS;
            int c  = idx2 >> 15;
            int r  = idx2 & 32767;
            int n  = r >> 3;
            int u  = r & 7;
            int k0 = c * CH_K + u * 8;
            __half2 h[4];
            if (k0 < K_DIM) {
                const int* qp = qw + (size_t)n * K_DIM + k0;
                int4 q0 = *(const int4*)qp;
                int4 q1 = *(const int4*)(qp + 4);
                int g = k0 >> 7;
                float s = scales[g * N_DIM + n];
                float z = zeros[g * N_DIM + n];
                h[0] = __floats2half2_rn((float)q0.x * s + z, (float)q0.y * s + z);
                h[1] = __floats2half2_rn((float)q0.z * s + z, (float)q0.w * s + z);
                h[2] = __floats2half2_rn((float)q1.x * s + z, (float)q1.y * s + z);
                h[3] = __floats2half2_rn((float)q1.z * s + z, (float)q1.w * s + z);
            } else {
                const float* op = ow + (size_t)n * NOUT + (k0 - K_DIM);
                float4 o0 = *(const float4*)op;
                float4 o1 = *(const float4*)(op + 4);
                h[0] = __floats2half2_rn(o0.x, o0.y);
                h[1] = __floats2half2_rn(o0.z, o0.w);
                h[2] = __floats2half2_rn(o1.x, o1.y);
                h[3] = __floats2half2_rn(o1.z, o1.w);
            }
            char* dst = (char*)g_We + ((size_t)c * N_DIM + n) * 128 + ((u ^ (n & 7)) << 4);
            *(uint4*)dst = *(uint4*)h;
        }
    }
}

// ===========================================================================
// Persistent cg2 tcgen05 GEMM — R14 topology (local full + relay), 7 stages.
// ===========================================================================
#if HAS_TCGEN05
__device__ __forceinline__ uint32_t smem_u32(const void* p) {
    return (uint32_t)__cvta_generic_to_shared(p);
}
__device__ __forceinline__ uint32_t elect_one() {
    uint32_t pred;
    asm volatile("{.reg .pred p; elect.sync _|p, 0xFFFFFFFF; selp.b32 %0, 1, 0, p;}"
                 : "=r"(pred));
    return pred;
}
__device__ __forceinline__ void mma_f16_ss_cg2(uint32_t d, uint64_t ad, uint64_t bd,
                                               uint32_t idesc, uint32_t accum) {
    asm volatile(
        "{.reg .pred p; setp.ne.u32 p, %5, 0;\n\t"
        "tcgen05.mma.cta_group::2.kind::f16 [%0], %1, %2, %3, "
        "{%4,%4,%4,%4,%4,%4,%4,%4}, p;}\n"
        :: "r"(d), "l"(ad), "l"(bd), "r"(idesc), "r"(0u), "r"(accum) : "memory");
}
__device__ __forceinline__ void mbar_wait(uint32_t addr, uint32_t parity) {
    asm volatile(
        "{.reg .pred P1;\n\t"
        "LAB_WAIT_%=:\n\t"
        "mbarrier.try_wait.parity.acquire.cta.shared::cta.b64 P1, [%0], %1, 0x989680;\n\t"
        "@P1 bra LAB_DONE_%=;\n\t"
        "bra LAB_WAIT_%=;\n\t"
        "LAB_DONE_%=:}\n"
        :: "r"(addr), "r"(parity) : "memory");
}
__device__ __forceinline__ void mbar_arrive_rank0(uint32_t addr) {
    asm volatile(
        "{.reg .b32 remAddr;\n\t"
        "mapa.shared::cluster.u32 remAddr, %0, 0;\n\t"
        "mbarrier.arrive.shared::cluster.b64 _, [remAddr];}\n"
        :: "r"(addr) : "memory");
}
#endif

extern __shared__ __align__(1024) char smn[];

__global__ void __launch_bounds__(256, 1) __cluster_dims__(2, 1, 1)
gemm_persist(const float* __restrict__ bias, float* __restrict__ y) {
#if HAS_TCGEN05
    const int tid  = threadIdx.x;
    const int w    = tid >> 5;
    const int lane = tid & 31;
    const int pid  = blockIdx.x >> 1;                  // pair id 0..73
    uint32_t rank;
    asm("mov.u32 %0, %%cluster_ctarank;" : "=r"(rank));
    const int niters = (NTILE2 - 1 - pid) / NPAIR + 1; // 7 for pid<68 else 6

    const uint32_t sbase    = smem_u32(smn);
    const uint32_t ctrl     = sbase + CTRL_OFF;
    const uint32_t mb_full  = ctrl + 8;                // 7: local chunk loaded (tx)
    const uint32_t mb_pair  = ctrl + 64;               // 7: leader, count 2
    const uint32_t mb_empt  = ctrl + 120;              // 7: buffer free (count 1)
    const uint32_t mb_done  = ctrl + 176;              // 2: tile MMA done (count 1)
    const uint32_t mb_lfree = ctrl + 192;              // 2: local epi done (count 128)
    const uint32_t mb_pfree = ctrl + 208;              // 2: leader, count 2

    if (w == 0) {
        asm volatile("tcgen05.alloc.cta_group::2.sync.aligned.shared::cta.b32 [%0], %1;"
                     :: "r"(ctrl), "r"(512u) : "memory");
        asm volatile("tcgen05.relinquish_alloc_permit.cta_group::2.sync.aligned;");
    }
    if (tid == 0) {
#pragma unroll
        for (int s = 0; s < NSTAGE; s++) {
            asm volatile("mbarrier.init.shared.b64 [%0], 1;" :: "r"(mb_full + 8 * s) : "memory");
            asm volatile("mbarrier.init.shared.b64 [%0], 2;" :: "r"(mb_pair + 8 * s) : "memory");
            asm volatile("mbarrier.init.shared.b64 [%0], 1;" :: "r"(mb_empt + 8 * s) : "memory");
        }
#pragma unroll
        for (int b = 0; b < 2; b++) {
            asm volatile("mbarrier.init.shared.b64 [%0], 1;"   :: "r"(mb_done + 8 * b)  : "memory");
            asm volatile("mbarrier.init.shared.b64 [%0], 128;" :: "r"(mb_lfree + 8 * b) : "memory");
            asm volatile("mbarrier.init.shared.b64 [%0], 2;"   :: "r"(mb_pfree + 8 * b) : "memory");
        }
    }
    __syncthreads();
    // All cluster mbarriers visible before any cross-CTA arrive/commit.
    asm volatile("barrier.cluster.arrive.aligned;" ::: "memory");
    asm volatile("barrier.cluster.wait.aligned;" ::: "memory");

    uint32_t tmem;
    asm volatile("ld.shared.b32 %0, [%1];" : "=r"(tmem) : "r"(ctrl));

    if (w == 0) {
        // ---------------- Leader MMA warp (rank 0 only) -------------------
        if (rank == 0 && elect_one()) {
            asm volatile("tcgen05.fence::after_thread_sync;" ::: "memory");
            int s = 0, ph = 0;
            for (int i = 0; i < niters; i++) {
                if (i >= 2) mbar_wait(mb_pfree + 8 * (i & 1), (uint32_t)(((i - 2) >> 1) & 1));
                const uint32_t d = tmem + (uint32_t)((i & 1) * 256);
                for (int c = 0; c < NCHUNK; c++) {
                    mbar_wait(mb_pair + 8 * s, (uint32_t)(ph & 1));
                    const uint32_t aAddr = sbase + s * STG_BYTES;
                    const uint64_t ad = DESC_BASE | ((aAddr >> 4) & 0x3FFF);
                    const uint64_t bd = DESC_BASE | (((aAddr + A_STG_BYTES) >> 4) & 0x3FFF);
#pragma unroll
                    for (int kk = 0; kk < 4; kk++)
                        mma_f16_ss_cg2(d, ad + kk * 2, bd + kk * 2, IDESC,
                                       (c > 0 || kk > 0) ? 1u : 0u);
                    // Buffer free in BOTH CTAs (MMA reads peer SMEM too).
                    asm volatile(
                        "tcgen05.commit.cta_group::2.mbarrier::arrive::one.shared::cluster"
                        ".multicast::cluster.b64 [%0], %1;"
                        :: "r"(mb_empt + 8 * s), "h"((uint16_t)0x3) : "memory");
                    if (++s == NSTAGE) { s = 0; ph++; }
                }
                // Tile done -> both CTAs drain their TMEM half.
                asm volatile(
                    "tcgen05.commit.cta_group::2.mbarrier::arrive::one.shared::cluster"
                    ".multicast::cluster.b64 [%0], %1;"
                    :: "r"(mb_done + 8 * (i & 1)), "h"((uint16_t)0x3) : "memory");
            }
        }
    } else if (w == 1) {
        // ---------------- Producer warp (own A slice + own B half) -------
        if (elect_one()) {
            int s = 0, ph = 0;
            for (int i = 0; i < niters; i++) {
                const int tile = pid + NPAIR * i;
                const int bm = ((tile >> 4) << 8) + (int)rank * TM;  // m slow
                const int bn = (tile & 15) << 8;                     // n FAST (B resident)
                for (int c = 0; c < NCHUNK; c++) {
                    if (ph > 0)
                        mbar_wait(mb_empt + 8 * s, (uint32_t)((ph - 1) & 1));
                    asm volatile("mbarrier.arrive.expect_tx.shared.b64 _, [%0], %1;"
                                 :: "r"(mb_full + 8 * s), "r"((uint32_t)STG_BYTES) : "memory");
                    const uint32_t dstA = sbase + s * STG_BYTES;
                    const char* srcA = (const char*)g_Xe + ((size_t)c * M_DIM + bm) * 128;
                    asm volatile(
                        "cp.async.bulk.shared::cluster.global.mbarrier::complete_tx::bytes "
                        "[%0], [%1], %2, [%3];"
                        :: "r"(dstA), "l"(srcA), "r"((uint32_t)A_STG_BYTES),
                           "r"(mb_full + 8 * s) : "memory");
                    const char* srcB = (const char*)g_We +
                                       ((size_t)c * N_DIM + bn + (int)rank * (TN / 2)) * 128;
                    asm volatile(
                        "cp.async.bulk.shared::cluster.global.mbarrier::complete_tx::bytes "
                        "[%0], [%1], %2, [%3];"
                        :: "r"(dstA + A_STG_BYTES), "l"(srcB), "r"((uint32_t)B_STG_BYTES),
                           "r"(mb_full + 8 * s) : "memory");
                    if (++s == NSTAGE) { s = 0; ph++; }
                }
            }
        }
    } else if (w == 2) {
        // ---------------- Full-relay: local full -> leader pair-full -----
        if (elect_one()) {
            int s = 0, ph = 0;
            for (int i = 0; i < niters; i++)
                for (int c = 0; c < NCHUNK; c++) {
                    mbar_wait(mb_full + 8 * s, (uint32_t)(ph & 1));
                    mbar_arrive_rank0(mb_pair + 8 * s);
                    if (++s == NSTAGE) { s = 0; ph++; }
                }
        }
    } else if (w == 3) {
        // ---------------- Free-relay: local epi done -> leader pair-free --
        if (elect_one()) {
            for (int i = 0; i < niters; i++) {
                mbar_wait(mb_lfree + 8 * (i & 1), (uint32_t)((i >> 1) & 1));
                mbar_arrive_rank0(mb_pfree + 8 * (i & 1));
            }
        }
    } else {
        // ---------------- Epilogue warps 4-7: drain own TMEM half --------
        const uint32_t warp_off = (uint32_t)((tid & 127) >> 5) << 21;
        const int ew = w - 4;
        for (int i = 0; i < niters; i++) {
            mbar_wait(mb_done + 8 * (i & 1), (uint32_t)((i >> 1) & 1));
            asm volatile("tcgen05.fence::after_thread_sync;" ::: "memory");
            const int tile = pid + NPAIR * i;
            const int bm = ((tile >> 4) << 8) + (int)rank * TM;
            const int bn = (tile & 15) << 8;
            const int m  = bm + (ew << 5) + lane;
            float* yrow = y + (size_t)m * N_DIM;
            const uint32_t dBase = tmem + (uint32_t)((i & 1) * 256) + warp_off;
#pragma unroll
            for (int cb = 0; cb < TN; cb += 32) {
                uint32_t r[32];
                asm volatile(
                    "tcgen05.ld.sync.aligned.32x32b.x32.b32 "
                    "{%0,%1,%2,%3,%4,%5,%6,%7,%8,%9,%10,%11,%12,%13,%14,%15,"
                    "%16,%17,%18,%19,%20,%21,%22,%23,%24,%25,%26,%27,%28,%29,%30,%31}, [%32];"
                    : "=r"(r[0]), "=r"(r[1]), "=r"(r[2]), "=r"(r[3]), "=r"(r[4]),
                      "=r"(r[5]), "=r"(r[6]), "=r"(r[7]), "=r"(r[8]), "=r"(r[9]),
                      "=r"(r[10]), "=r"(r[11]), "=r"(r[12]), "=r"(r[13]), "=r"(r[14]),
                      "=r"(r[15]), "=r"(r[16]), "=r"(r[17]), "=r"(r[18]), "=r"(r[19]),
                      "=r"(r[20]), "=r"(r[21]), "=r"(r[22]), "=r"(r[23]), "=r"(r[24]),
                      "=r"(r[25]), "=r"(r[26]), "=r"(r[27]), "=r"(r[28]), "=r"(r[29]),
                      "=r"(r[30]), "=r"(r[31])
                    : "r"(dBase + (uint32_t)cb));
                asm volatile("tcgen05.wait::ld.sync.aligned;" ::: "memory");
                const int col0 = bn + cb;
#pragma unroll
                for (int q = 0; q < 8; q++) {
                    float4 bv = *(const float4*)(bias + col0 + q * 4);
                    float4 o;
                    o.x = __uint_as_float(r[q * 4 + 0]) + bv.x;
                    o.y = __uint_as_float(r[q * 4 + 1]) + bv.y;
                    o.z = __uint_as_float(r[q * 4 + 2]) + bv.z;
                    o.w = __uint_as_float(r[q * 4 + 3]) + bv.w;
                    *(float4*)(yrow + col0 + q * 4) = o;
                }
            }
            asm volatile("tcgen05.fence::before_thread_sync;" ::: "memory");
            asm volatile("mbarrier.arrive.shared.b64 _, [%0];"
                         :: "r"(mb_lfree + 8 * (i & 1)) : "memory");
        }
    }

    __syncthreads();
    if (w == 0) {
        asm volatile("tcgen05.dealloc.cta_group::2.sync.aligned.b32 %0, %1;"
                     :: "r"(tmem), "r"(512u));
    }
    // No CTA may exit while the peer may still touch its SMEM/TMEM.
    asm volatile("barrier.cluster.arrive.aligned;" ::: "memory");
    asm volatile("barrier.cluster.wait.aligned;" ::: "memory");
#endif  // HAS_TCGEN05
}

// ===========================================================================
// Fallback: mma.sync (compiled only when tcgen05 is unavailable); reads the
// tiled pre-swizzled gmem layout produced by prep_all.
// ===========================================================================
__global__ __launch_bounds__(256, 2) void gemm_f16(const float* __restrict__ bias,
                                                   float* __restrict__ y) {
#if !HAS_TCGEN05
    __shared__ __align__(16) __half As[3][128 * 32];
    __shared__ __align__(16) __half Bs[3][128 * 32];

    const int t    = threadIdx.x;
    const int lane = t & 31;
    const int w    = t >> 5;
    const int bm   = blockIdx.y << 7;
    const int bn   = blockIdx.x << 7;
    const int wm   = (w >> 2) << 6;
    const int wn   = (w & 3) << 5;

    const int lr = t >> 2;
    const int lc = t & 3;

    float acc[4][4][4];
#pragma unroll
    for (int i = 0; i < 4; i++)
#pragma unroll
        for (int j = 0; j < 4; j++)
#pragma unroll
            for (int r = 0; r < 4; r++) acc[i][j][r] = 0.f;

    unsigned sA = (unsigned)__cvta_generic_to_shared(As);
    unsigned sB = (unsigned)__cvta_generic_to_shared(Bs);

    auto swz = [](int row, int chunk) {
        return (row << 5) + ((chunk ^ ((row >> 1) & 3)) << 3);
    };
    auto gaddr = [](const __half* base, int rows_total, int grow, int ks, int u4) {
        int c  = ks >> 1;
        int cu = ((ks & 1) << 2) + u4;
        return (const char*)base + ((size_t)c * rows_total + grow) * 128 +
               ((cu ^ (grow & 7)) << 4);
    };

    auto load_stage = [&](int buf, int ks) {
#pragma unroll
        for (int i = 0; i < 2; i++) {
            int row = lr + (i << 6);
            unsigned da = sA + (unsigned)((buf * 4096 + swz(row, lc)) << 1);
            const char* ga = gaddr(g_Xe, M_DIM, bm + row, ks, lc);
            asm volatile("cp.async.cg.shared.global [%0], [%1], 16;\n" ::"r"(da), "l"(ga));
            unsigned db = sB + (unsigned)((buf * 4096 + swz(row, lc)) << 1);
            const char* gb = gaddr(g_We, N_DIM, bn + row, ks, lc);
            asm volatile("cp.async.cg.shared.global [%0], [%1], 16;\n" ::"r"(db), "l"(gb));
        }
    };

    const int NSTEP = KE / 32;
    load_stage(0, 0);
    asm volatile("cp.async.commit_group;\n");
    load_stage(1, 1);
    asm volatile("cp.async.commit_group;\n");

    const int a_row  = wm + (lane & 15);
    const int a_cofs = lane >> 4;
    const int b_row  = wn + (lane & 7) + ((lane >> 4) << 3);
    const int b_cofs = (lane >> 3) & 1;

    for (int ks = 0; ks < NSTEP; ks++) {
        asm volatile("cp.async.wait_group 1;\n");
        __syncthreads();
        int buf = ks % 3;
        if (ks + 2 < NSTEP) load_stage((ks + 2) % 3, ks + 2);
        asm volatile("cp.async.commit_group;\n");

        unsigned baseA = sA + (unsigned)(buf * 8192);
        unsigned baseB = sB + (unsigned)(buf * 8192);

#pragma unroll
        for (int p = 0; p < 2; p++) {
            unsigned a[4][4];
#pragma unroll
            for (int i = 0; i < 4; i++) {
                int row = a_row + (i << 4);
                int chunk = (p << 1) + a_cofs;
                unsigned addr = baseA + (unsigned)(swz(row, chunk) << 1);
                asm volatile(
                    "ldmatrix.sync.aligned.m8n8.x4.shared.b16 {%0,%1,%2,%3}, [%4];\n"
                    : "=r"(a[i][0]), "=r"(a[i][1]), "=r"(a[i][2]), "=r"(a[i][3])
                    : "r"(addr));
            }
            unsigned b[4][2];
#pragma unroll
            for (int jj = 0; jj < 2; jj++) {
                int row = b_row + (jj << 4);
                int chunk = (p << 1) + b_cofs;
                unsigned addr = baseB + (unsigned)(swz(row, chunk) << 1);
                unsigned r0, r1, r2, r3;
                asm volatile(
                    "ldmatrix.sync.aligned.m8n8.x4.shared.b16 {%0,%1,%2,%3}, [%4];\n"
                    : "=r"(r0), "=r"(r1), "=r"(r2), "=r"(r3)
                    : "r"(addr));
                b[jj * 2][0] = r0; b[jj * 2][1] = r1;
                b[jj * 2 + 1][0] = r2; b[jj * 2 + 1][1] = r3;
            }
#pragma unroll
            for (int i = 0; i < 4; i++)
#pragma unroll
                for (int j = 0; j < 4; j++)
                    asm volatile(
                        "mma.sync.aligned.m16n8k16.row.col.f32.f16.f16.f32 "
                        "{%0,%1,%2,%3}, {%4,%5,%6,%7}, {%8,%9}, {%0,%1,%2,%3};\n"
                        : "+f"(acc[i][j][0]), "+f"(acc[i][j][1]),
                          "+f"(acc[i][j][2]), "+f"(acc[i][j][3])
                        : "r"(a[i][0]), "r"(a[i][1]), "r"(a[i][2]), "r"(a[i][3]),
                          "r"(b[j][0]), "r"(b[j][1]));
        }
    }

#pragma unroll
    for (int i = 0; i < 4; i++) {
        int row = bm + wm + (i << 4) + (lane >> 2);
#pragma unroll
        for (int j = 0; j < 4; j++) {
            int col = bn + wn + (j << 3) + ((lane & 3) << 1);
            float2 bb = *(const float2*)(bias + col);
            float2 o0 = make_float2(acc[i][j][0] + bb.x, acc[i][j][1] + bb.y);
            float2 o1 = make_float2(acc[i][j][2] + bb.x, acc[i][j][3] + bb.y);
            *(float2*)(y + (size_t)row * N_DIM + col)       = o0;
            *(float2*)(y + (size_t)(row + 8) * N_DIM + col) = o1;
        }
    }
#endif  // !HAS_TCGEN05
}

// ---------------------------------------------------------------------------
extern "C" void kernel_launch(void* const* d_in, const int* in_sizes, int n_in,
                              void* d_out, int out_size) {
    const float* x      = (const float*)d_in[0];
    const int*   qw     = (const int*)d_in[1];
    const float* scales = (const float*)d_in[2];
    const float* zeros  = (const float*)d_in[3];
    const float* ow     = (const float*)d_in[4];
    const float* bias   = (const float*)d_in[5];
    float*       y      = (float*)d_out;

    prep_all<<<PREP_BLOCKS, 256>>>(x, qw, scales, zeros, ow);

    // Exactly one GEMM kernel has a real body (decided at device-compile time);
    // the real one is the one with more registers. Pure host query, capture-safe.
    cudaFuncAttributes aT{}, aF{};
    cudaFuncGetAttributes(&aT, gemm_persist);
    cudaFuncGetAttributes(&aF, gemm_f16);

    if (aT.numRegs >= aF.numRegs) {
        cudaFuncSetAttribute(gemm_persist, cudaFuncAttributeMaxDynamicSharedMemorySize,
                             SMEM_TOTAL);
        gemm_persist<<<NCTA, 256, SMEM_TOTAL>>>(bias, y);   // 74 clusters of 2
    } else {
        dim3 gridF(N_DIM / 128, M_DIM / 128);
        gemm_f16<<<gridF, 256>>>(bias, y);
    }
}